// round 4
// baseline (speedup 1.0000x reference)
#include <cuda_runtime.h>
#include <cuda_bf16.h>

#define L 45
#define LP 48              // padded label count
#define SMAX 512
#define START_IDX 43
#define STOP_IDX 44
#define PF 4               // logit prefetch distance
#define LOG2E 1.4426950408889634f
#define LN2   0.6931471805599453f
#define FULLM 0xFFFFFFFFu

__device__ __forceinline__ float ex2f(float x) {
    float r; asm("ex2.approx.ftz.f32 %0, %1;" : "=f"(r) : "f"(x)); return r;
}
__device__ __forceinline__ float lg2f(float x) {
    float r; asm("lg2.approx.ftz.f32 %0, %1;" : "=f"(r) : "f"(x)); return r;
}
__device__ __forceinline__ void fma2(unsigned long long& d,
                                     unsigned long long a, unsigned long long b) {
    asm("fma.rn.f32x2 %0, %1, %2, %0;" : "+l"(d) : "l"(a), "l"(b));
}
__device__ __forceinline__ void add2(unsigned long long& d, unsigned long long a) {
    asm("add.rn.f32x2 %0, %0, %1;" : "+l"(d) : "l"(a));
}
__device__ __forceinline__ unsigned long long pack2(float lo, float hi) {
    unsigned long long v;
    asm("mov.b64 %0, {%1, %2};" : "=l"(v) : "f"(lo), "f"(hi)); return v;
}
__device__ __forceinline__ float2 unpack2(unsigned long long v) {
    float2 f; asm("mov.b64 {%0, %1}, %2;" : "=f"(f.x), "=f"(f.y) : "l"(v)); return f;
}

// ONE WARP PER BATCH ELEMENT, 4 warps (4 batches) per 128-thread block so the
// warps land on all four SMSPs (wid%4). No cross-warp barriers at all: the
// e-vector exchange is per-warp smem + __syncwarp.
// Lane k owns label rows k (dot A) and k+32 (dot B, lanes 0..12). Lane 31's
// spare dot-B slot redundantly computes row 0 (s_0) and produces the scale
// increment c (lg2 runs in parallel with everyone's ex2).
// Recurrence (base-2, scaled-linear): s_i = sum_j expT[i,j]*e[j];
//   e'_i = s_i * 2^(lgt2_i - c2);  M2 += c2;  c2' = lg2(s_0)+lgt2_0-c2 (stale).
__global__ __launch_bounds__(128) void crf_fwd_kernel(
    const float* __restrict__ logits,      // [B, S, L]
    const int*   __restrict__ lens,        // [B]
    const float* __restrict__ trans,       // [L, L], trans[i*L+j]=score(j->i)
    float*       __restrict__ out)         // [B]
{
    const int w = threadIdx.x >> 5;        // warp in block (0..3)
    const int k = threadIdx.x & 31;        // lane
    const int b = blockIdx.x * 4 + w;

    __shared__ __align__(16) float e_sm[4][2][LP];
    __shared__ float c_sm[4][2];
    float (*e_s)[LP] = e_sm[w];
    float* c_s = c_sm[w];

    const bool hasB = (k < 13);            // owns real second label k+32
    const bool isC  = (k == 31);           // produces c from duplicate row 0
    const int labA = k;
    const int labB = hasB ? (k + 32) : 0;  // lane 31 -> row 0; 13..30 unused
    const bool ldB = hasB | isC;

    // packed expT rows in registers (pairs over j)
    unsigned long long rowpA[LP / 2], rowpB[LP / 2];
#pragma unroll
    for (int m = 0; m < LP / 2; m++) {
        const float a0 = __expf(trans[labA * L + 2 * m]);
        const float a1 = (2 * m + 1 < L) ? __expf(trans[labA * L + 2 * m + 1]) : 0.f;
        rowpA[m] = pack2(a0, a1);
        float b0 = 0.f, b1 = 0.f;
        if (ldB) {
            b0 = __expf(trans[labB * L + 2 * m]);
            b1 = (2 * m + 1 < L) ? __expf(trans[labB * L + 2 * m + 1]) : 0.f;
        }
        rowpB[m] = pack2(b0, b1);
    }

    const int len = lens[b];
    const float* lg = logits + (size_t)b * SMAX * L;

    // zero both e buffers (pad lanes 45..47 stay 0 forever)
    if (k < 16) {
#pragma unroll
        for (int q = 0; q < 3; q++) { e_s[0][k + 16 * q] = 0.f; e_s[1][k + 16 * q] = 0.f; }
    }
    if (k == 0) { c_s[0] = 0.f; c_s[1] = 0.f; }

    // ---- t = 0 analytically: alpha0 = logit[0] + T[:, START] ----
    const float a0A = lg[labA] + trans[labA * L + START_IDX];
    const float a0B = hasB ? (lg[labB] + trans[labB * L + START_IDX]) : 0.f;
    const float mu0 = __shfl_sync(FULLM, a0A, 0);
    float M2 = mu0 * LOG2E;
    float e_locA = ex2f((a0A - mu0) * LOG2E);
    float e_locB = hasB ? ex2f((a0B - mu0) * LOG2E) : 0.f;
    __syncwarp();                           // zeroing done before overwrite
    e_s[1][k] = e_locA;
    if (hasB) e_s[1][k + 32] = e_locB;

    // ---- prefetch logits (pre-scaled by log2e) ----
    float lgA[PF], lgB[PF];
#pragma unroll
    for (int u = 0; u < PF; u++) {
        const int t = 1 + u;
        lgA[u] = (t < len) ? lg[t * L + labA] * LOG2E : 0.f;
        lgB[u] = (ldB && t < len) ? lg[t * L + labB] * LOG2E : 0.f;
    }

#define STEP(tt, uu) do {                                                     \
        const int p_ = (tt) & 1;                                              \
        __syncwarp();                                                         \
        const float lgtA_ = lgA[uu];                                          \
        const float lgtB_ = lgB[uu];                                          \
        { const int tn_ = (tt) + PF;                                          \
          lgA[uu] = (tn_ < len) ? lg[tn_ * L + labA] * LOG2E : 0.f;           \
          lgB[uu] = (ldB && tn_ < len) ? lg[tn_ * L + labB] * LOG2E : 0.f; }  \
        const float c2_ = c_s[p_ ^ 1];                                        \
        const ulonglong2* e2_ = (const ulonglong2*)(e_s[p_]);                 \
        unsigned long long aA_[4] = {0,0,0,0}, aB_[4] = {0,0,0,0};            \
        _Pragma("unroll")                                                     \
        for (int h_ = 0; h_ < LP / 4; h_++) {                                 \
            const ulonglong2 wv_ = e2_[h_];                                   \
            fma2(aA_[(2 * h_)     & 3], rowpA[2 * h_],     wv_.x);            \
            fma2(aB_[(2 * h_)     & 3], rowpB[2 * h_],     wv_.x);            \
            fma2(aA_[(2 * h_ + 1) & 3], rowpA[2 * h_ + 1], wv_.y);            \
            fma2(aB_[(2 * h_ + 1) & 3], rowpB[2 * h_ + 1], wv_.y);            \
        }                                                                     \
        add2(aA_[0], aA_[2]); add2(aA_[1], aA_[3]); add2(aA_[0], aA_[1]);     \
        add2(aB_[0], aB_[2]); add2(aB_[1], aB_[3]); add2(aB_[0], aB_[1]);     \
        const float2 fA_ = unpack2(aA_[0]);                                   \
        const float2 fB_ = unpack2(aB_[0]);                                   \
        const float sA_ = fA_.x + fA_.y;                                      \
        const float sB_ = fB_.x + fB_.y;                                      \
        const float enA_ = sA_ * ex2f(lgtA_ - c2_);                           \
        e_s[p_ ^ 1][k] = enA_; e_locA = enA_;                                 \
        if (hasB) {                                                           \
            const float enB_ = sB_ * ex2f(lgtB_ - c2_);                       \
            e_s[p_ ^ 1][k + 32] = enB_; e_locB = enB_;                        \
        }                                                                     \
        if (isC) c_s[p_] = lg2f(sB_) + lgtB_ - c2_;                           \
        M2 += c2_;                                                            \
    } while (0)

    // main loop: full PF-chunks, uniform branches only (len uniform per warp)
    int t = 1;
    for (; t + PF <= len; t += PF) {
        STEP(t + 0, 0);
        STEP(t + 1, 1);
        STEP(t + 2, 2);
        STEP(t + 3, 3);
    }
    // tail (<= 3 steps), constant lgbuf indices
    if (t < len) { STEP(t, 0); t++; }
    if (t < len) { STEP(t, 1); t++; }
    if (t < len) { STEP(t, 2); }
#undef STEP

    // ---- epilogue: warp-level LSE over 45 alphas ----
    const float vA = (M2 + lg2f(e_locA)) * LN2 + trans[STOP_IDX * L + labA];
    const float vB = hasB ? ((M2 + lg2f(e_locB)) * LN2 + trans[STOP_IDX * L + labB])
                          : -1e30f;
    float m = fmaxf(vA, vB);
#pragma unroll
    for (int off = 16; off; off >>= 1)
        m = fmaxf(m, __shfl_xor_sync(FULLM, m, off));
    float s = ex2f((vA - m) * LOG2E) + (hasB ? ex2f((vB - m) * LOG2E) : 0.f);
#pragma unroll
    for (int off = 16; off; off >>= 1)
        s += __shfl_xor_sync(FULLM, s, off);
    if (k == 0) out[b] = m + lg2f(s) * LN2;
}

extern "C" void kernel_launch(void* const* d_in, const int* in_sizes, int n_in,
                              void* d_out, int out_size) {
    const float* logits = (const float*)d_in[0];   // [1024, 512, 45] f32
    const int*   lens   = (const int*)d_in[1];     // [1024] i32
    const float* trans  = (const float*)d_in[2];   // [45, 45] f32
    float* out = (float*)d_out;                    // [1024] f32

    const int B = in_sizes[1];                     // 1024
    crf_fwd_kernel<<<B / 4, 128>>>(logits, lens, trans, out);
}